// round 15
// baseline (speedup 1.0000x reference)
#include <cuda_runtime.h>
#include <cuda_fp16.h>
#include <cstdint>

// ---------------------------------------------------------------------------
// out = sum_p w_p * kron8(blocks[idx[p]])  -> 256x256
// G[a,b] = sum_p (w_p A_p[a]) B_p[b];  out[(iH16+iL),(jH16+jL)] = G[iH16+jH, iL16+jL]
// A = w*ternary -> split w = w_hi + w_lo (fp16): A_hi, A_lo, B exact fp16.
// G = A_hi^T B + A_lo^T B via mma.sync f16->f32, tiles generated in smem.
// R15: NO split-K partials, NO reduce kernel. Epilogue does red.global.add.v2.f32
//      straight into d_out with the Kronecker permutation in the address.
//      d_out zeroed per replay by a cudaMemsetAsync graph node.
// ---------------------------------------------------------------------------

#define POP      4096
#define SPLITK   16
#define KCHUNK   256                 // 16*256 = 4096 exactly
#define KSTEPS   16                  // 256/16
#define LDTA     72                  // A tile row stride (halfs), 64 + pad
#define LDTB     136                 // B tile row stride (halfs), 128 + pad

// ---------------- warp-MMA helpers (sm_80+ PTX, valid at compute_103) ------
__device__ __forceinline__ unsigned smem_u32(const void* p) {
    unsigned a;
    asm("{ .reg .u64 t; cvta.to.shared.u64 t, %1; cvt.u32.u64 %0, t; }" : "=r"(a) : "l"(p));
    return a;
}
__device__ __forceinline__ void ldsm_x4_t(uint32_t* r, unsigned a) {
    asm volatile("ldmatrix.sync.aligned.m8n8.x4.trans.shared.b16 {%0,%1,%2,%3}, [%4];"
                 : "=r"(r[0]), "=r"(r[1]), "=r"(r[2]), "=r"(r[3]) : "r"(a));
}
__device__ __forceinline__ void ldsm_x2_t(uint32_t* r, unsigned a) {
    asm volatile("ldmatrix.sync.aligned.m8n8.x2.trans.shared.b16 {%0,%1}, [%2];"
                 : "=r"(r[0]), "=r"(r[1]) : "r"(a));
}
__device__ __forceinline__ void mma16816(float* d, const uint32_t* a, const uint32_t* b) {
    asm volatile("mma.sync.aligned.m16n8k16.row.col.f32.f16.f16.f32 "
                 "{%0,%1,%2,%3}, {%4,%5,%6,%7}, {%8,%9}, {%0,%1,%2,%3};"
                 : "+f"(d[0]), "+f"(d[1]), "+f"(d[2]), "+f"(d[3])
                 : "r"(a[0]), "r"(a[1]), "r"(a[2]), "r"(a[3]), "r"(b[0]), "r"(b[1]));
}
__device__ __forceinline__ void red_add_v2(float* p, float x, float y) {
    asm volatile("red.global.add.v2.f32 [%0], {%1, %2};"
                 :: "l"(p), "f"(x), "f"(y) : "memory");
}

// ---------------------------------------------------------------------------
// Fused kernel: grid (4 mb, 2 nb, 16 z) = 128 CTAs, 512 threads (16 warps).
// Phases: stage consts -> V-tables -> build A hi/lo + B in smem -> HMMA ->
// atomic epilogue into permuted d_out.
// ---------------------------------------------------------------------------
__global__ void __launch_bounds__(512, 1) fused_kernel(
        const float* __restrict__ w,
        const int*   __restrict__ idxg,
        const float* __restrict__ bbg,
        float*       __restrict__ out) {
    extern __shared__ __half smem[];
    __half* As = smem;                               // [KCHUNK][LDTA]
    __half* Al = smem + KCHUNK * LDTA;
    __half* Bs = smem + 2 * KCHUNK * LDTA;           // [KCHUNK][LDTB]
    __shared__ float bb[144];
    __shared__ int   sidx[KCHUNK * 8];
    __shared__ float sw[KCHUNK];
    __shared__ uint4 vt[4 * KCHUNK];                 // V-tables: 2 uint4/entry

    const int tid = threadIdx.x, lane = tid & 31, wid = tid >> 5;
    const int mb = blockIdx.x, nb = blockIdx.y, z = blockIdx.z;
    const int gbase = z * KCHUNK;

    // ---- Stage constants (no guards: 16*256 = 4096 exactly) ----
    if (tid < 144) bb[tid] = bbg[tid];
    #pragma unroll
    for (int i = tid; i < KCHUNK * 8; i += 512)
        sidx[i] = __ldg(&idxg[gbase * 8 + i]);
    if (tid < KCHUNK) sw[tid] = __ldg(&w[gbase + tid]);
    __syncthreads();

    // ---- V-tables: one per (genome, side), 512 tasks ----
    {
        const int i = tid;
        const int gl = i & (KCHUNK - 1);
        const int cb = (i < KCHUNK) ? 2 : 6;
        const int ia = sidx[gl * 8 + cb], ib = sidx[gl * 8 + cb + 1];
        __half2 Vh[8];
        #pragma unroll
        for (int p = 0; p < 2; p++)
          #pragma unroll
          for (int q = 0; q < 2; q++)
            #pragma unroll
            for (int r = 0; r < 2; r++) {
                const float va = bb[ia * 4 + p * 2 + r];
                Vh[((p*2+q)*4 + r*2) >> 1] =
                    __floats2half2_rn(va * bb[ib * 4 + q * 2],
                                      va * bb[ib * 4 + q * 2 + 1]);
            }
        uint4 u0, u1;
        u0.x = *(unsigned*)&Vh[0]; u0.y = *(unsigned*)&Vh[1];
        u0.z = *(unsigned*)&Vh[2]; u0.w = *(unsigned*)&Vh[3];
        u1.x = *(unsigned*)&Vh[4]; u1.y = *(unsigned*)&Vh[5];
        u1.z = *(unsigned*)&Vh[6]; u1.w = *(unsigned*)&Vh[7];
        vt[i * 2]     = u0;
        vt[i * 2 + 1] = u1;
    }
    __syncthreads();

    // ---- Build A hi/lo: tasks (gl, xi), xi 0..3; x = mb*4 + xi ----
    #pragma unroll
    for (int i = tid; i < KCHUNK * 4; i += 512) {
        const int gl = i >> 2, xi = i & 3;
        const float u = bb[sidx[gl*8+0] * 4 + (mb >> 1) * 2 + (xi >> 1)]
                      * bb[sidx[gl*8+1] * 4 + (mb & 1) * 2 + (xi & 1)];
        const float wf  = sw[gl];
        const float whf = __half2float(__float2half_rn(wf));
        const float wlf = __half2float(__float2half_rn(wf - whf));
        const __half2 ph = __float2half2_rn(whf * u);   // exact {0, +/-w_hi}
        const __half2 pl = __float2half2_rn(wlf * u);

        const uint4 v0 = vt[gl * 2], v1 = vt[gl * 2 + 1];
        const unsigned vv[8] = {v0.x, v0.y, v0.z, v0.w, v1.x, v1.y, v1.z, v1.w};
        #pragma unroll
        for (int qq = 0; qq < 4; qq++) {
            const __half2 a0 = *(const __half2*)&vv[2*qq];
            const __half2 a1 = *(const __half2*)&vv[2*qq+1];
            __half2 h0 = __hmul2(ph, a0), h1 = __hmul2(ph, a1);
            __half2 l0 = __hmul2(pl, a0), l1 = __hmul2(pl, a1);
            const int col = (qq << 4) | (xi << 2);
            uint2 uh; uh.x = *(unsigned*)&h0; uh.y = *(unsigned*)&h1;
            uint2 ul; ul.x = *(unsigned*)&l0; ul.y = *(unsigned*)&l1;
            *(uint2*)&As[gl * LDTA + col] = uh;
            *(uint2*)&Al[gl * LDTA + col] = ul;
        }
    }

    // ---- Build B: tasks (gl, xi), xi 0..7; x = nb*8 + xi ----
    #pragma unroll
    for (int i = tid; i < KCHUNK * 8; i += 512) {
        const int gl = i >> 3, xi = i & 7;
        const float u = bb[sidx[gl*8+4] * 4 + nb * 2 + ((xi >> 1) & 1)]
                      * bb[sidx[gl*8+5] * 4 + ((xi >> 2) & 1) * 2 + (xi & 1)];
        const __half2 uh2 = __float2half2_rn(u);

        const uint4 v0 = vt[(KCHUNK + gl) * 2], v1 = vt[(KCHUNK + gl) * 2 + 1];
        const unsigned vv[8] = {v0.x, v0.y, v0.z, v0.w, v1.x, v1.y, v1.z, v1.w};
        const int colbase = (((xi >> 2) & 1) << 6) | ((xi & 3) << 2);
        #pragma unroll
        for (int qq = 0; qq < 4; qq++) {
            const __half2 a0 = *(const __half2*)&vv[2*qq];
            const __half2 a1 = *(const __half2*)&vv[2*qq+1];
            __half2 h0 = __hmul2(uh2, a0), h1 = __hmul2(uh2, a1);
            const int col = colbase | (qq << 4);
            uint2 uv; uv.x = *(unsigned*)&h0; uv.y = *(unsigned*)&h1;
            *(uint2*)&Bs[gl * LDTB + col] = uv;
        }
    }
    __syncthreads();

    // ---- HMMA mainloop: 16 warps, 16x32 warp tiles ----
    const int wm = wid & 3;
    const int wn = wid >> 2;
    const int arow = (lane & 7) + ((lane >> 4) << 3);
    const int acol = wm * 16 + ((lane >> 3) & 1) * 8;
    const int bl = lane & 15;
    const int brow = (bl & 7) + ((bl >> 3) << 3);

    const unsigned aHi = smem_u32(&As[arow * LDTA + acol]);
    const unsigned aLo = smem_u32(&Al[arow * LDTA + acol]);
    const unsigned bBa = smem_u32(&Bs[brow * LDTB + wn * 32]);

    float acc[4][4];
    #pragma unroll
    for (int j = 0; j < 4; j++)
        #pragma unroll
        for (int q = 0; q < 4; q++) acc[j][q] = 0.f;

    #pragma unroll
    for (int ks = 0; ks < KSTEPS; ks++) {
        const unsigned koa = (unsigned)(ks * 16 * LDTA * 2);
        const unsigned kob = (unsigned)(ks * 16 * LDTB * 2);
        uint32_t bf[4][2];
        #pragma unroll
        for (int nt = 0; nt < 4; nt++) ldsm_x2_t(bf[nt], bBa + kob + nt * 16);
        uint32_t ah[4], al[4];
        ldsm_x4_t(ah, aHi + koa);
        ldsm_x4_t(al, aLo + koa);
        #pragma unroll
        for (int nt = 0; nt < 4; nt++) {
            mma16816(acc[nt], ah, bf[nt]);
            mma16816(acc[nt], al, bf[nt]);
        }
    }

    // ---- Atomic epilogue: red.global.add.v2.f32 into permuted d_out ----
    // a = r0 + (lane>>2) (+8), b = c0 + nt*8 + (lane&3)*2 (b, b+1 same 16-grp)
    // out[(a>>4)*4096 + (b>>4)*256 + (a&15)*16 + (b&15)]
    const int r0 = mb * 64 + wm * 16;
    const int c0 = nb * 128 + wn * 32;
    const int a1 = r0 + (lane >> 2);
    const int a2 = a1 + 8;
    float* base1 = out + ((a1 >> 4) << 12) + ((a1 & 15) << 4);
    float* base2 = out + ((a2 >> 4) << 12) + ((a2 & 15) << 4);
    #pragma unroll
    for (int nt = 0; nt < 4; nt++) {
        const int b = c0 + nt * 8 + (lane & 3) * 2;
        const int boff = ((b >> 4) << 8) + (b & 15);
        red_add_v2(base1 + boff, acc[nt][0], acc[nt][1]);
        red_add_v2(base2 + boff, acc[nt][2], acc[nt][3]);
    }
}

extern "C" void kernel_launch(void* const* d_in, const int* in_sizes, int n_in,
                              void* d_out, int out_size) {
    const float* w   = (const float*)d_in[0];
    const int*   idx = (const int*)  d_in[1];
    const float* bb  = (const float*)d_in[2];

    const int smem_bytes = (2 * KCHUNK * LDTA + KCHUNK * LDTB) * (int)sizeof(__half); // 143360
    cudaFuncSetAttribute(fused_kernel, cudaFuncAttributeMaxDynamicSharedMemorySize, smem_bytes);

    // Zero the accumulation target each replay (memset node in the graph).
    cudaMemsetAsync(d_out, 0, (size_t)out_size * sizeof(float), 0);

    fused_kernel<<<dim3(4, 2, SPLITK), 512, smem_bytes>>>(w, idx, bb, (float*)d_out);
}

// round 16
// speedup vs baseline: 1.2179x; 1.2179x over previous
#include <cuda_runtime.h>
#include <cuda_fp16.h>
#include <cstdint>

// ---------------------------------------------------------------------------
// out = sum_p w_p * kron8(blocks[idx[p]])  -> 256x256
// G[a,b] = sum_p (w_p A_p[a]) B_p[b];  out[(iH16+iL),(jH16+jL)] = G[iH16+jH, iL16+jL]
// A = w*ternary -> split w = w_hi + w_lo (fp16): A_hi, A_lo, B exact fp16.
// G = A_hi^T B + A_lo^T B via mma.sync f16->f32, tiles generated in smem.
// R15: atomic epilogue (red.global.add.v2.f32) straight into permuted d_out.
// R16: NO memset node. z==0 CTAs zero their d_out slice as their first
//      instructions; all 128 CTAs are wave-1 co-resident and every atomic
//      is >=10K cycles behind the zero-stores (same L2 coherence point).
// ---------------------------------------------------------------------------

#define POP      4096
#define SPLITK   16
#define KCHUNK   256                 // 16*256 = 4096 exactly
#define KSTEPS   16                  // 256/16
#define LDTA     72                  // A tile row stride (halfs), 64 + pad
#define LDTB     136                 // B tile row stride (halfs), 128 + pad

// ---------------- warp-MMA helpers (sm_80+ PTX, valid at compute_103) ------
__device__ __forceinline__ unsigned smem_u32(const void* p) {
    unsigned a;
    asm("{ .reg .u64 t; cvta.to.shared.u64 t, %1; cvt.u32.u64 %0, t; }" : "=r"(a) : "l"(p));
    return a;
}
__device__ __forceinline__ void ldsm_x4_t(uint32_t* r, unsigned a) {
    asm volatile("ldmatrix.sync.aligned.m8n8.x4.trans.shared.b16 {%0,%1,%2,%3}, [%4];"
                 : "=r"(r[0]), "=r"(r[1]), "=r"(r[2]), "=r"(r[3]) : "r"(a));
}
__device__ __forceinline__ void ldsm_x2_t(uint32_t* r, unsigned a) {
    asm volatile("ldmatrix.sync.aligned.m8n8.x2.trans.shared.b16 {%0,%1}, [%2];"
                 : "=r"(r[0]), "=r"(r[1]) : "r"(a));
}
__device__ __forceinline__ void mma16816(float* d, const uint32_t* a, const uint32_t* b) {
    asm volatile("mma.sync.aligned.m16n8k16.row.col.f32.f16.f16.f32 "
                 "{%0,%1,%2,%3}, {%4,%5,%6,%7}, {%8,%9}, {%0,%1,%2,%3};"
                 : "+f"(d[0]), "+f"(d[1]), "+f"(d[2]), "+f"(d[3])
                 : "r"(a[0]), "r"(a[1]), "r"(a[2]), "r"(a[3]), "r"(b[0]), "r"(b[1]));
}
__device__ __forceinline__ void red_add_v2(float* p, float x, float y) {
    asm volatile("red.global.add.v2.f32 [%0], {%1, %2};"
                 :: "l"(p), "f"(x), "f"(y) : "memory");
}

// ---------------------------------------------------------------------------
// Fused kernel: grid (4 mb, 2 nb, 16 z) = 128 CTAs, 512 threads (16 warps).
// ---------------------------------------------------------------------------
__global__ void __launch_bounds__(512, 1) fused_kernel(
        const float* __restrict__ w,
        const int*   __restrict__ idxg,
        const float* __restrict__ bbg,
        float*       __restrict__ out) {
    extern __shared__ __half smem[];
    __half* As = smem;                               // [KCHUNK][LDTA]
    __half* Al = smem + KCHUNK * LDTA;
    __half* Bs = smem + 2 * KCHUNK * LDTA;           // [KCHUNK][LDTB]
    __shared__ float bb[144];
    __shared__ int   sidx[KCHUNK * 8];
    __shared__ float sw[KCHUNK];
    __shared__ uint4 vt[4 * KCHUNK];                 // V-tables: 2 uint4/entry

    const int tid = threadIdx.x, lane = tid & 31, wid = tid >> 5;
    const int mb = blockIdx.x, nb = blockIdx.y, z = blockIdx.z;
    const int gbase = z * KCHUNK;

    // ---- FIRST: z==0 CTAs zero their 8192-float slice of d_out. Committed
    // to L2 within ~600cyc; every CTA's first atomic is >=10K cycles away. ----
    if (z == 0) {
        float4* dst = (float4*)out + (mb * 2 + nb) * 2048 + tid;
        const float4 z4 = make_float4(0.f, 0.f, 0.f, 0.f);
        dst[0] = z4; dst[512] = z4; dst[1024] = z4; dst[1536] = z4;
    }

    // ---- Stage constants (no guards: 16*256 = 4096 exactly) ----
    if (tid < 144) bb[tid] = bbg[tid];
    #pragma unroll
    for (int i = tid; i < KCHUNK * 8; i += 512)
        sidx[i] = __ldg(&idxg[gbase * 8 + i]);
    if (tid < KCHUNK) sw[tid] = __ldg(&w[gbase + tid]);
    __syncthreads();

    // ---- V-tables: one per (genome, side), 512 tasks ----
    {
        const int i = tid;
        const int gl = i & (KCHUNK - 1);
        const int cb = (i < KCHUNK) ? 2 : 6;
        const int ia = sidx[gl * 8 + cb], ib = sidx[gl * 8 + cb + 1];
        __half2 Vh[8];
        #pragma unroll
        for (int p = 0; p < 2; p++)
          #pragma unroll
          for (int q = 0; q < 2; q++)
            #pragma unroll
            for (int r = 0; r < 2; r++) {
                const float va = bb[ia * 4 + p * 2 + r];
                Vh[((p*2+q)*4 + r*2) >> 1] =
                    __floats2half2_rn(va * bb[ib * 4 + q * 2],
                                      va * bb[ib * 4 + q * 2 + 1]);
            }
        uint4 u0, u1;
        u0.x = *(unsigned*)&Vh[0]; u0.y = *(unsigned*)&Vh[1];
        u0.z = *(unsigned*)&Vh[2]; u0.w = *(unsigned*)&Vh[3];
        u1.x = *(unsigned*)&Vh[4]; u1.y = *(unsigned*)&Vh[5];
        u1.z = *(unsigned*)&Vh[6]; u1.w = *(unsigned*)&Vh[7];
        vt[i * 2]     = u0;
        vt[i * 2 + 1] = u1;
    }
    __syncthreads();

    // ---- Build A hi/lo: tasks (gl, xi), xi 0..3; x = mb*4 + xi ----
    #pragma unroll
    for (int i = tid; i < KCHUNK * 4; i += 512) {
        const int gl = i >> 2, xi = i & 3;
        const float u = bb[sidx[gl*8+0] * 4 + (mb >> 1) * 2 + (xi >> 1)]
                      * bb[sidx[gl*8+1] * 4 + (mb & 1) * 2 + (xi & 1)];
        const float wf  = sw[gl];
        const float whf = __half2float(__float2half_rn(wf));
        const float wlf = __half2float(__float2half_rn(wf - whf));
        const __half2 ph = __float2half2_rn(whf * u);   // exact {0, +/-w_hi}
        const __half2 pl = __float2half2_rn(wlf * u);

        const uint4 v0 = vt[gl * 2], v1 = vt[gl * 2 + 1];
        const unsigned vv[8] = {v0.x, v0.y, v0.z, v0.w, v1.x, v1.y, v1.z, v1.w};
        #pragma unroll
        for (int qq = 0; qq < 4; qq++) {
            const __half2 a0 = *(const __half2*)&vv[2*qq];
            const __half2 a1 = *(const __half2*)&vv[2*qq+1];
            __half2 h0 = __hmul2(ph, a0), h1 = __hmul2(ph, a1);
            __half2 l0 = __hmul2(pl, a0), l1 = __hmul2(pl, a1);
            const int col = (qq << 4) | (xi << 2);
            uint2 uh; uh.x = *(unsigned*)&h0; uh.y = *(unsigned*)&h1;
            uint2 ul; ul.x = *(unsigned*)&l0; ul.y = *(unsigned*)&l1;
            *(uint2*)&As[gl * LDTA + col] = uh;
            *(uint2*)&Al[gl * LDTA + col] = ul;
        }
    }

    // ---- Build B: tasks (gl, xi), xi 0..7; x = nb*8 + xi ----
    #pragma unroll
    for (int i = tid; i < KCHUNK * 8; i += 512) {
        const int gl = i >> 3, xi = i & 7;
        const float u = bb[sidx[gl*8+4] * 4 + nb * 2 + ((xi >> 1) & 1)]
                      * bb[sidx[gl*8+5] * 4 + ((xi >> 2) & 1) * 2 + (xi & 1)];
        const __half2 uh2 = __float2half2_rn(u);

        const uint4 v0 = vt[(KCHUNK + gl) * 2], v1 = vt[(KCHUNK + gl) * 2 + 1];
        const unsigned vv[8] = {v0.x, v0.y, v0.z, v0.w, v1.x, v1.y, v1.z, v1.w};
        const int colbase = (((xi >> 2) & 1) << 6) | ((xi & 3) << 2);
        #pragma unroll
        for (int qq = 0; qq < 4; qq++) {
            const __half2 a0 = *(const __half2*)&vv[2*qq];
            const __half2 a1 = *(const __half2*)&vv[2*qq+1];
            __half2 h0 = __hmul2(uh2, a0), h1 = __hmul2(uh2, a1);
            const int col = colbase | (qq << 4);
            uint2 uv; uv.x = *(unsigned*)&h0; uv.y = *(unsigned*)&h1;
            *(uint2*)&Bs[gl * LDTB + col] = uv;
        }
    }
    __syncthreads();

    // ---- HMMA mainloop: 16 warps, 16x32 warp tiles ----
    const int wm = wid & 3;
    const int wn = wid >> 2;
    const int arow = (lane & 7) + ((lane >> 4) << 3);
    const int acol = wm * 16 + ((lane >> 3) & 1) * 8;
    const int bl = lane & 15;
    const int brow = (bl & 7) + ((bl >> 3) << 3);

    const unsigned aHi = smem_u32(&As[arow * LDTA + acol]);
    const unsigned aLo = smem_u32(&Al[arow * LDTA + acol]);
    const unsigned bBa = smem_u32(&Bs[brow * LDTB + wn * 32]);

    float acc[4][4];
    #pragma unroll
    for (int j = 0; j < 4; j++)
        #pragma unroll
        for (int q = 0; q < 4; q++) acc[j][q] = 0.f;

    #pragma unroll
    for (int ks = 0; ks < KSTEPS; ks++) {
        const unsigned koa = (unsigned)(ks * 16 * LDTA * 2);
        const unsigned kob = (unsigned)(ks * 16 * LDTB * 2);
        uint32_t bf[4][2];
        #pragma unroll
        for (int nt = 0; nt < 4; nt++) ldsm_x2_t(bf[nt], bBa + kob + nt * 16);
        uint32_t ah[4], al[4];
        ldsm_x4_t(ah, aHi + koa);
        ldsm_x4_t(al, aLo + koa);
        #pragma unroll
        for (int nt = 0; nt < 4; nt++) {
            mma16816(acc[nt], ah, bf[nt]);
            mma16816(acc[nt], al, bf[nt]);
        }
    }

    // ---- Atomic epilogue: red.global.add.v2.f32 into permuted d_out ----
    // out[(a>>4)*4096 + (b>>4)*256 + (a&15)*16 + (b&15)]
    const int r0 = mb * 64 + wm * 16;
    const int c0 = nb * 128 + wn * 32;
    const int a1 = r0 + (lane >> 2);
    const int a2 = a1 + 8;
    float* base1 = out + ((a1 >> 4) << 12) + ((a1 & 15) << 4);
    float* base2 = out + ((a2 >> 4) << 12) + ((a2 & 15) << 4);
    #pragma unroll
    for (int nt = 0; nt < 4; nt++) {
        const int b = c0 + nt * 8 + (lane & 3) * 2;
        const int boff = ((b >> 4) << 8) + (b & 15);
        red_add_v2(base1 + boff, acc[nt][0], acc[nt][1]);
        red_add_v2(base2 + boff, acc[nt][2], acc[nt][3]);
    }
}

extern "C" void kernel_launch(void* const* d_in, const int* in_sizes, int n_in,
                              void* d_out, int out_size) {
    const float* w   = (const float*)d_in[0];
    const int*   idx = (const int*)  d_in[1];
    const float* bb  = (const float*)d_in[2];

    const int smem_bytes = (2 * KCHUNK * LDTA + KCHUNK * LDTB) * (int)sizeof(__half); // 143360
    cudaFuncSetAttribute(fused_kernel, cudaFuncAttributeMaxDynamicSharedMemorySize, smem_bytes);

    fused_kernel<<<dim3(4, 2, SPLITK), 512, smem_bytes>>>(w, idx, bb, (float*)d_out);
}